// round 6
// baseline (speedup 1.0000x reference)
#include <cuda_runtime.h>
#include <cuda_bf16.h>
#include <cstdint>

// Problem constants
#define B_  8
#define TE_ 256
#define TD_ 128
#define HE_ 512

// Scratch: Ws = enc @ W_a  [B, TE, HE], Uh = dec @ U_a  [B, TD, HE]
__device__ float g_Ws[B_ * TE_ * HE_];   // 4 MB
__device__ float g_Uh[B_ * TD_ * HE_];   // 2 MB

// Packed fp32x2 FMA (Blackwell): d = a*b + d elementwise on 2-wide fp32.
#define FFMA2(acc, a, b) \
    asm("fma.rn.f32x2 %0, %1, %2, %0;" : "+l"(acc) : "l"(a), "l"(b))
#define PACK_DUP(dst, x) \
    asm("mov.b64 %0, {%1, %1};" : "=l"(dst) : "f"(x))
#define UNPACK2(lo, hi, in) \
    asm("mov.b64 {%0, %1}, %2;" : "=f"(lo), "=f"(hi) : "l"(in))

// ---------------------------------------------------------------------------
// Kernel 1: combined GEMM.  C[M,512] = A[M,512] x Bmat[512,512], fp32,
// inner product via packed fma.rn.f32x2 (2 MACs/issue).
// 64x64 tile, BK=16, 128 threads, 8x4 microtile (4 M-row-pairs x 4 N-cols).
// Blocks 0..255   -> GEMM0 (Ws, M=2048: 32x8 tiles)
// Blocks 256..383 -> GEMM1 (Uh, M=1024: 16x8 tiles)
// ---------------------------------------------------------------------------
#define GBK 16
#define AS_STRIDE 68   // 64 + 4 pad; 68*4=272B row pitch, 16B-aligned

__global__ __launch_bounds__(128) void gemm_kernel(
    const float* __restrict__ enc, const float* __restrict__ dec,
    const float* __restrict__ Wa,  const float* __restrict__ Ua)
{
    __shared__ float As[GBK * AS_STRIDE];  // As[k][m]
    __shared__ float Bs[GBK * 64];         // Bs[k][n]

    const int bx = blockIdx.x;
    const float* A;
    const float* Bm;
    float* C;
    int mtile, ntile;
    if (bx < 256) {
        A = enc; Bm = Wa; C = g_Ws;
        mtile = bx >> 3; ntile = bx & 7;      // 32 x 8
    } else {
        int b2 = bx - 256;
        A = dec; Bm = Ua; C = g_Uh;
        mtile = b2 >> 3; ntile = b2 & 7;      // 16 x 8
    }
    const int m0 = mtile * 64;
    const int n0 = ntile * 64;

    const int tid = threadIdx.x;
    const int tx = tid & 15;      // 16 -> 4 cols each
    const int ty = tid >> 4;      // 8  -> 8 rows each (4 packed pairs)

    const int ar = tid >> 2;           // 0..31 (rows ar, ar+32)
    const int ak = (tid & 3) * 4;      // k-quad
    const int br = tid >> 4;           // 0..7 (rows br, br+8)
    const int bn = (tid & 15) * 4;

    // acc[p][j]: packed pair = rows (ty*8+2p, ty*8+2p+1), col tx*4+j
    uint64_t acc[4][4];
    #pragma unroll
    for (int p = 0; p < 4; p++)
        #pragma unroll
        for (int j = 0; j < 4; j++) acc[p][j] = 0ull;

    // prefetch first tile
    float4 pA0 = *(const float4*)&A[(m0 + ar)      * 512 + ak];
    float4 pA1 = *(const float4*)&A[(m0 + ar + 32) * 512 + ak];
    float4 pB0 = *(const float4*)&Bm[(br)     * 512 + n0 + bn];
    float4 pB1 = *(const float4*)&Bm[(br + 8) * 512 + n0 + bn];

    for (int k0 = 0; k0 < 512; k0 += GBK) {
        if (k0 > 0) __syncthreads();
        As[(ak + 0) * AS_STRIDE + ar] = pA0.x;
        As[(ak + 1) * AS_STRIDE + ar] = pA0.y;
        As[(ak + 2) * AS_STRIDE + ar] = pA0.z;
        As[(ak + 3) * AS_STRIDE + ar] = pA0.w;
        As[(ak + 0) * AS_STRIDE + ar + 32] = pA1.x;
        As[(ak + 1) * AS_STRIDE + ar + 32] = pA1.y;
        As[(ak + 2) * AS_STRIDE + ar + 32] = pA1.z;
        As[(ak + 3) * AS_STRIDE + ar + 32] = pA1.w;
        *(float4*)&Bs[br       * 64 + bn] = pB0;
        *(float4*)&Bs[(br + 8) * 64 + bn] = pB1;
        __syncthreads();

        if (k0 + GBK < 512) {
            int kn = k0 + GBK;
            pA0 = *(const float4*)&A[(m0 + ar)      * 512 + kn + ak];
            pA1 = *(const float4*)&A[(m0 + ar + 32) * 512 + kn + ak];
            pB0 = *(const float4*)&Bm[(kn + br)     * 512 + n0 + bn];
            pB1 = *(const float4*)&Bm[(kn + br + 8) * 512 + n0 + bn];
        }

        #pragma unroll
        for (int k = 0; k < GBK; k++) {
            // a row-pairs: 8 contiguous floats -> 2x LDS.128 (4 u64 pairs)
            const ulonglong2* a128 =
                (const ulonglong2*)&As[k * AS_STRIDE + ty * 8];
            ulonglong2 aL = a128[0];
            ulonglong2 aH = a128[1];
            // b: 4 scalars, duplicated into packed pairs (ALU pipe)
            float4 b4 = *(float4*)&Bs[k * 64 + tx * 4];
            uint64_t bd0, bd1, bd2, bd3;
            PACK_DUP(bd0, b4.x);
            PACK_DUP(bd1, b4.y);
            PACK_DUP(bd2, b4.z);
            PACK_DUP(bd3, b4.w);

            FFMA2(acc[0][0], aL.x, bd0); FFMA2(acc[0][1], aL.x, bd1);
            FFMA2(acc[0][2], aL.x, bd2); FFMA2(acc[0][3], aL.x, bd3);
            FFMA2(acc[1][0], aL.y, bd0); FFMA2(acc[1][1], aL.y, bd1);
            FFMA2(acc[1][2], aL.y, bd2); FFMA2(acc[1][3], aL.y, bd3);
            FFMA2(acc[2][0], aH.x, bd0); FFMA2(acc[2][1], aH.x, bd1);
            FFMA2(acc[2][2], aH.x, bd2); FFMA2(acc[2][3], aH.x, bd3);
            FFMA2(acc[3][0], aH.y, bd0); FFMA2(acc[3][1], aH.y, bd1);
            FFMA2(acc[3][2], aH.y, bd2); FFMA2(acc[3][3], aH.y, bd3);
        }
    }

    // Writeback: each packed pair holds (row 2p, row 2p+1) for col tx*4+j.
    #pragma unroll
    for (int p = 0; p < 4; p++) {
        float lo[4], hi[4];
        #pragma unroll
        for (int j = 0; j < 4; j++) UNPACK2(lo[j], hi[j], acc[p][j]);
        float4 vlo = {lo[0], lo[1], lo[2], lo[3]};
        float4 vhi = {hi[0], hi[1], hi[2], hi[3]};
        *(float4*)&C[(m0 + ty * 8 + 2 * p)     * 512 + n0 + tx * 4] = vlo;
        *(float4*)&C[(m0 + ty * 8 + 2 * p + 1) * 512 + n0 + tx * 4] = vhi;
    }
}

// ---------------------------------------------------------------------------
// Kernel 2: fused  e = softmax_t( V . tanh(Ws[b,t,:] + Uh[b,d,:]) ),
//                  c = e @ enc[b]
// Grid: (B, TD/8).  320 threads = 10 warps:
//   warps 0..7  : compute (warp w owns decoder step d0+w), MUFU-bound
//                 (8.2K cyc/SMSP per tile)
//   warps 8..9  : dedicated stagers double-buffering Ws tiles; unroll 16
//                 gives MLP~16 -> ~4-5K cyc per 64KB tile, fully hidden.
// Ws tiles in shared as ws[h][t_local], row stride 33 (conflict-free
// transposed writes AND conflict-free per-lane reads).
// ---------------------------------------------------------------------------
#define WS_TILE (512 * 33)
#define SMEM_FLOATS (2 * WS_TILE + 8 * 512 + 512 + 8 * 256)

__device__ __forceinline__ float f4_get(const float4& v, int j) {
    switch (j) {
        case 0: return v.x;
        case 1: return v.y;
        case 2: return v.z;
        default: return v.w;
    }
}

__global__ __launch_bounds__(320) void attn_kernel(
    const float* __restrict__ enc, const float* __restrict__ Va,
    float* __restrict__ out_c, float* __restrict__ out_e)
{
    extern __shared__ float sm[];
    float* ws_buf = sm;                       // [2][512][33]
    float* uh_s = sm + 2 * WS_TILE;           // [8][512]
    float* v_s  = uh_s + 8 * 512;             // [512]
    float* sw   = v_s + 512;                  // [8][256] softmax weights

    const int b  = blockIdx.x;
    const int d0 = blockIdx.y * 8;
    const int tid  = threadIdx.x;
    const int w    = tid >> 5;                // warp id
    const int lane = tid & 31;

    const float* Wsb = g_Ws + b * TE_ * HE_;

    // Stage V, the 8 Uh rows, and Ws tile 0 (all 320 threads)
    for (int i = tid; i < 512; i += 320) v_s[i] = Va[i];
    const float* Uh = g_Uh + (b * TD_ + d0) * HE_;
    for (int i = tid; i < 8 * 512; i += 320) uh_s[i] = Uh[i];
    #pragma unroll 4
    for (int i = tid; i < 32 * 512; i += 320) {
        int t = i >> 9;
        int h = i & 511;
        ws_buf[h * 33 + t] = Wsb[t * 512 + h];
    }
    __syncthreads();

    float eacc[8];
    const float* uh = uh_s + (w & 7) * 512;

    for (int tt = 0; tt < 8; tt++) {
        if (w < 8) {
            // ---- compute on buffer tt&1 ----
            const float* ws = ws_buf + (tt & 1) * WS_TILE;
            float e = 0.f;
            #pragma unroll 2
            for (int h = 0; h < 512; h += 4) {
                float4 u4 = *(const float4*)&uh[h];
                float4 v4 = *(const float4*)&v_s[h];
                float x0 = ws[(h + 0) * 33 + lane] + u4.x;
                float x1 = ws[(h + 1) * 33 + lane] + u4.y;
                float x2 = ws[(h + 2) * 33 + lane] + u4.z;
                float x3 = ws[(h + 3) * 33 + lane] + u4.w;
                float t0, t1, t2, t3;
                asm("tanh.approx.f32 %0, %1;" : "=f"(t0) : "f"(x0));
                asm("tanh.approx.f32 %0, %1;" : "=f"(t1) : "f"(x1));
                asm("tanh.approx.f32 %0, %1;" : "=f"(t2) : "f"(x2));
                asm("tanh.approx.f32 %0, %1;" : "=f"(t3) : "f"(x3));
                e = fmaf(v4.x, t0, e);
                e = fmaf(v4.y, t1, e);
                e = fmaf(v4.z, t2, e);
                e = fmaf(v4.w, t3, e);
            }
            eacc[tt] = e;
        } else if (tt + 1 < 8) {
            // ---- stager warps: fill buffer (tt+1)&1 with tile tt+1 ----
            // unroll 16 => ~16 outstanding LDGs => L2 latency amortized.
            float* ws_d = ws_buf + ((tt + 1) & 1) * WS_TILE;
            const float* src = Wsb + (tt + 1) * 32 * 512;
            const int s = tid - 256;          // 0..63 across 2 warps
            #pragma unroll 16
            for (int j = 0; j < 256; j++) {
                int idx = s + j * 64;         // 0..16383
                int t = idx >> 9;
                int h = idx & 511;            // consecutive h per lane: coalesced
                ws_d[h * 33 + t] = src[t * 512 + h];
            }
        }
        __syncthreads();
    }

    // Per-warp softmax over 256 logits (8 regs x 32 lanes), t = tt*32 + lane
    if (w < 8) {
        float m = eacc[0];
        #pragma unroll
        for (int i = 1; i < 8; i++) m = fmaxf(m, eacc[i]);
        #pragma unroll
        for (int o = 16; o > 0; o >>= 1) m = fmaxf(m, __shfl_xor_sync(0xffffffffu, m, o));
        float s = 0.f;
        #pragma unroll
        for (int i = 0; i < 8; i++) { eacc[i] = __expf(eacc[i] - m); s += eacc[i]; }
        #pragma unroll
        for (int o = 16; o > 0; o >>= 1) s += __shfl_xor_sync(0xffffffffu, s, o);
        const float inv = 1.f / s;

        float* erow = out_e + (size_t)(b * TD_ + d0 + w) * TE_;
        #pragma unroll
        for (int i = 0; i < 8; i++) {
            float wv = eacc[i] * inv;
            sw[w * 256 + i * 32 + lane] = wv;
            erow[i * 32 + lane] = wv;
        }
    }
    __syncthreads();

    // Context: c[d0+d][h] = sum_t sw[d][t] * enc[b][t][h]
    // Threads 0..255: thread owns h pair {2*tid, 2*tid+1}.
    if (tid < 256) {
        float2 cacc[8];
        #pragma unroll
        for (int d = 0; d < 8; d++) cacc[d] = make_float2(0.f, 0.f);
        const float* encb = enc + (size_t)b * TE_ * HE_;
        const int h2 = tid * 2;
        for (int t0 = 0; t0 < TE_; t0 += 4) {
            float4 w4[8];
            #pragma unroll
            for (int d = 0; d < 8; d++) w4[d] = *(const float4*)&sw[d * 256 + t0];
            #pragma unroll
            for (int j = 0; j < 4; j++) {
                float2 ev = *(const float2*)&encb[(t0 + j) * 512 + h2];
                #pragma unroll
                for (int d = 0; d < 8; d++) {
                    float wv = f4_get(w4[d], j);
                    cacc[d].x = fmaf(wv, ev.x, cacc[d].x);
                    cacc[d].y = fmaf(wv, ev.y, cacc[d].y);
                }
            }
        }
        #pragma unroll
        for (int d = 0; d < 8; d++) {
            float* crow = out_c + (size_t)(b * TD_ + d0 + d) * HE_;
            *(float2*)&crow[h2] = cacc[d];
        }
    }
}

// ---------------------------------------------------------------------------
extern "C" void kernel_launch(void* const* d_in, const int* in_sizes, int n_in,
                              void* d_out, int out_size)
{
    const float* enc = (const float*)d_in[0];   // [8,256,512]
    const float* dec = (const float*)d_in[1];   // [8,128,512]
    const float* Wa  = (const float*)d_in[2];   // [512,512]
    const float* Ua  = (const float*)d_in[3];   // [512,512]
    const float* Va  = (const float*)d_in[4];   // [512,1]

    float* out   = (float*)d_out;
    float* out_c = out;                          // [8,128,512]
    float* out_e = out + B_ * TD_ * HE_;         // [8,128,256]

    gemm_kernel<<<384, 128>>>(enc, dec, Wa, Ua);

    const int smem_bytes = SMEM_FLOATS * (int)sizeof(float);  // 165376 B
    cudaFuncSetAttribute(attn_kernel,
                         cudaFuncAttributeMaxDynamicSharedMemorySize, smem_bytes);
    attn_kernel<<<dim3(B_, TD_ / 8), 320, smem_bytes>>>(enc, Va, out_c, out_e);
}

// round 14
// speedup vs baseline: 2.1155x; 2.1155x over previous
#include <cuda_runtime.h>
#include <cuda_bf16.h>
#include <cstdint>

// Problem constants
#define B_  8
#define TE_ 256
#define TD_ 128
#define HE_ 512

// Scratch: WsT = (enc @ W_a)^T per batch: [B][HE][TE]; Uh = dec @ U_a [B][TD][HE]
__device__ float g_WsT[B_ * HE_ * TE_];  // 4 MB
__device__ float g_Uh[B_ * TD_ * HE_];   // 2 MB

// Packed fp32x2 FMA (Blackwell)
#define FFMA2(acc, a, b) \
    asm("fma.rn.f32x2 %0, %1, %2, %0;" : "+l"(acc) : "l"(a), "l"(b))
#define PACK_DUP(dst, x) \
    asm("mov.b64 %0, {%1, %1};" : "=l"(dst) : "f"(x))
#define UNPACK2(lo, hi, in) \
    asm("mov.b64 {%0, %1}, %2;" : "=f"(lo), "=f"(hi) : "l"(in))
#define TANHF(dst, x) \
    asm("tanh.approx.f32 %0, %1;" : "=f"(dst) : "f"(x))

// ---------------------------------------------------------------------------
// Kernel 1: combined GEMM, fp32 via fma.rn.f32x2, 64x64 tile, BK=16,
// 128 threads, 8x4 microtile (4 M-row-pairs x 4 N-cols).
// Blocks 0..255 : WsT[b][h][t] = sum_k Wa[k][h] * enc[b][t][k]
//                 (A = Wa read naturally into As[k][h]; B = enc transposed)
//                 per b: M=512(h) x N=256(t) -> 8x4 tiles; b = bx>>5
// Blocks 256..383: Uh = dec @ Ua, M=1024, N=512 -> 16x8 tiles
// ---------------------------------------------------------------------------
#define GBK 16
#define TS 68   // padded smem row stride (floats)

__global__ __launch_bounds__(128) void gemm_kernel(
    const float* __restrict__ enc, const float* __restrict__ dec,
    const float* __restrict__ Wa,  const float* __restrict__ Ua)
{
    __shared__ float As[GBK * TS];  // As[k][m]
    __shared__ float Bs[GBK * TS];  // Bs[k][n]

    const int bx = blockIdx.x;
    const int tid = threadIdx.x;
    const int tx = tid & 15;      // 4 cols each
    const int ty = tid >> 4;      // 8 rows each (4 packed pairs)

    const bool isT = (bx < 256);
    float* C;
    int m0, n0, cpitch;
    const float* Aenc;   // streaming operand (enc or dec)
    if (isT) {
        int b = bx >> 5;
        int t5 = bx & 31;
        m0 = (t5 >> 2) * 64;            // h
        n0 = (t5 & 3) * 64;             // t
        C = g_WsT + b * (HE_ * TE_);
        cpitch = TE_;
        Aenc = enc + (size_t)b * TE_ * HE_;
    } else {
        int b2 = bx - 256;
        m0 = (b2 >> 3) * 64;
        n0 = (b2 & 7) * 64;
        C = g_Uh;
        cpitch = HE_;
        Aenc = dec;
    }

    // ---- load index maps ----
    const int kr = tid >> 3;           // T-path A: k row (16)
    const int h4 = (tid & 7) * 4;      // T-path A: h quad
    const int t_r = tid >> 2;          // T-path B: t row (0..31, +32)
    const int kq = (tid & 3) * 4;      // T-path B: k quad
    const int ar = tid >> 2;           // U-path A rows ar, ar+32
    const int ak = (tid & 3) * 4;
    const int br = tid >> 4;           // U-path B rows br, br+8
    const int bn = (tid & 15) * 4;

    uint64_t acc[4][4];
    #pragma unroll
    for (int p = 0; p < 4; p++)
        #pragma unroll
        for (int j = 0; j < 4; j++) acc[p][j] = 0ull;

    // ---- prefetch first tiles ----
    float4 pA0, pA1, pB0, pB1;
    if (isT) {
        pA0 = *(const float4*)&Wa[(0 + kr) * 512 + m0 + h4];
        pA1 = *(const float4*)&Wa[(0 + kr) * 512 + m0 + h4 + 32];
        pB0 = *(const float4*)&Aenc[(n0 + t_r)      * 512 + kq];
        pB1 = *(const float4*)&Aenc[(n0 + t_r + 32) * 512 + kq];
    } else {
        pA0 = *(const float4*)&Aenc[(m0 + ar)      * 512 + ak];
        pA1 = *(const float4*)&Aenc[(m0 + ar + 32) * 512 + ak];
        pB0 = *(const float4*)&Ua[(br)     * 512 + n0 + bn];
        pB1 = *(const float4*)&Ua[(br + 8) * 512 + n0 + bn];
    }

    for (int k0 = 0; k0 < 512; k0 += GBK) {
        if (k0 > 0) __syncthreads();
        if (isT) {
            *(float4*)&As[kr * TS + h4]      = pA0;
            *(float4*)&As[kr * TS + h4 + 32] = pA1;
            Bs[(kq + 0) * TS + t_r] = pB0.x;
            Bs[(kq + 1) * TS + t_r] = pB0.y;
            Bs[(kq + 2) * TS + t_r] = pB0.z;
            Bs[(kq + 3) * TS + t_r] = pB0.w;
            Bs[(kq + 0) * TS + t_r + 32] = pB1.x;
            Bs[(kq + 1) * TS + t_r + 32] = pB1.y;
            Bs[(kq + 2) * TS + t_r + 32] = pB1.z;
            Bs[(kq + 3) * TS + t_r + 32] = pB1.w;
        } else {
            As[(ak + 0) * TS + ar] = pA0.x;
            As[(ak + 1) * TS + ar] = pA0.y;
            As[(ak + 2) * TS + ar] = pA0.z;
            As[(ak + 3) * TS + ar] = pA0.w;
            As[(ak + 0) * TS + ar + 32] = pA1.x;
            As[(ak + 1) * TS + ar + 32] = pA1.y;
            As[(ak + 2) * TS + ar + 32] = pA1.z;
            As[(ak + 3) * TS + ar + 32] = pA1.w;
            *(float4*)&Bs[br       * TS + bn] = pB0;
            *(float4*)&Bs[(br + 8) * TS + bn] = pB1;
        }
        __syncthreads();

        if (k0 + GBK < 512) {
            int kn = k0 + GBK;
            if (isT) {
                pA0 = *(const float4*)&Wa[(kn + kr) * 512 + m0 + h4];
                pA1 = *(const float4*)&Wa[(kn + kr) * 512 + m0 + h4 + 32];
                pB0 = *(const float4*)&Aenc[(n0 + t_r)      * 512 + kn + kq];
                pB1 = *(const float4*)&Aenc[(n0 + t_r + 32) * 512 + kn + kq];
            } else {
                pA0 = *(const float4*)&Aenc[(m0 + ar)      * 512 + kn + ak];
                pA1 = *(const float4*)&Aenc[(m0 + ar + 32) * 512 + kn + ak];
                pB0 = *(const float4*)&Ua[(kn + br)     * 512 + n0 + bn];
                pB1 = *(const float4*)&Ua[(kn + br + 8) * 512 + n0 + bn];
            }
        }

        #pragma unroll
        for (int k = 0; k < GBK; k++) {
            const ulonglong2* a128 = (const ulonglong2*)&As[k * TS + ty * 8];
            ulonglong2 aL = a128[0];
            ulonglong2 aH = a128[1];
            float4 b4 = *(float4*)&Bs[k * TS + tx * 4];
            uint64_t bd0, bd1, bd2, bd3;
            PACK_DUP(bd0, b4.x);
            PACK_DUP(bd1, b4.y);
            PACK_DUP(bd2, b4.z);
            PACK_DUP(bd3, b4.w);

            FFMA2(acc[0][0], aL.x, bd0); FFMA2(acc[0][1], aL.x, bd1);
            FFMA2(acc[0][2], aL.x, bd2); FFMA2(acc[0][3], aL.x, bd3);
            FFMA2(acc[1][0], aL.y, bd0); FFMA2(acc[1][1], aL.y, bd1);
            FFMA2(acc[1][2], aL.y, bd2); FFMA2(acc[1][3], aL.y, bd3);
            FFMA2(acc[2][0], aH.x, bd0); FFMA2(acc[2][1], aH.x, bd1);
            FFMA2(acc[2][2], aH.x, bd2); FFMA2(acc[2][3], aH.x, bd3);
            FFMA2(acc[3][0], aH.y, bd0); FFMA2(acc[3][1], aH.y, bd1);
            FFMA2(acc[3][2], aH.y, bd2); FFMA2(acc[3][3], aH.y, bd3);
        }
    }

    #pragma unroll
    for (int p = 0; p < 4; p++) {
        float lo[4], hi[4];
        #pragma unroll
        for (int j = 0; j < 4; j++) UNPACK2(lo[j], hi[j], acc[p][j]);
        float4 vlo = {lo[0], lo[1], lo[2], lo[3]};
        float4 vhi = {hi[0], hi[1], hi[2], hi[3]};
        *(float4*)&C[(m0 + ty * 8 + 2 * p)     * cpitch + n0 + tx * 4] = vlo;
        *(float4*)&C[(m0 + ty * 8 + 2 * p + 1) * cpitch + n0 + tx * 4] = vhi;
    }
}

// ---------------------------------------------------------------------------
// Kernel 2: high-occupancy fused logits + softmax + context.
// Grid (B, TD/4) = 256 CTAs x 512 threads = 16 warps (~21 KB smem,
// 3-4 CTAs/SM resident -> 48-64 warps/SM vs 10 in the R6 design).
// Warp w: d = d0 + (w>>2), t-quarter q = w&3; lane covers t = q*64 + 2*lane.
// Logits stream WsT[b][h][t] with coalesced LDG.64; the 4 warps sharing a
// quarter (di=0..3) read identical addresses -> L1-served after first touch.
// ---------------------------------------------------------------------------
__global__ __launch_bounds__(512) void attn_kernel(
    const float* __restrict__ enc, const float* __restrict__ Va,
    float* __restrict__ out_c, float* __restrict__ out_e)
{
    __shared__ float2 uv_s[4 * 512];   // (Uh[d][h], V[h]) per local d
    __shared__ float  sw4[256 * 4];    // softmax weights, float4 over d
    __shared__ float  red_m[16];
    __shared__ float  red_s[16];

    const int b   = blockIdx.x;
    const int d0  = blockIdx.y * 4;
    const int tid = threadIdx.x;
    const int w    = tid >> 5;
    const int lane = tid & 31;
    const int di = w >> 2;             // local d 0..3
    const int q  = w & 3;              // t-quarter

    // stage (uh, v) pairs
    const float* Uh = g_Uh + (size_t)(b * TD_ + d0) * HE_;
    for (int i = tid; i < 4 * 512; i += 512) {
        int dd = i >> 9, h = i & 511;
        uv_s[i] = make_float2(Uh[dd * 512 + h], Va[h]);
    }
    __syncthreads();

    // ---- logits: e[t], t = q*64 + 2*lane (+1) ----
    const float* wsrow = g_WsT + (size_t)b * (HE_ * TE_) + q * 64 + 2 * lane;
    const float2* uvd = &uv_s[di * 512];
    float e0 = 0.f, e1 = 0.f;
    #pragma unroll 16
    for (int h = 0; h < 512; h++) {
        float2 w2 = *(const float2*)&wsrow[h * 256];
        float2 uv = uvd[h];
        float x0 = w2.x + uv.x;
        float x1 = w2.y + uv.x;
        float t0, t1;
        TANHF(t0, x0);
        TANHF(t1, x1);
        e0 = fmaf(uv.y, t0, e0);
        e1 = fmaf(uv.y, t1, e1);
    }

    // ---- softmax over t (4 quarter-warps per d) ----
    float m = fmaxf(e0, e1);
    #pragma unroll
    for (int o = 16; o > 0; o >>= 1) m = fmaxf(m, __shfl_xor_sync(0xffffffffu, m, o));
    if (lane == 0) red_m[di * 4 + q] = m;
    __syncthreads();
    float M = fmaxf(fmaxf(red_m[di * 4 + 0], red_m[di * 4 + 1]),
                    fmaxf(red_m[di * 4 + 2], red_m[di * 4 + 3]));
    float p0 = __expf(e0 - M);
    float p1 = __expf(e1 - M);
    float s = p0 + p1;
    #pragma unroll
    for (int o = 16; o > 0; o >>= 1) s += __shfl_xor_sync(0xffffffffu, s, o);
    if (lane == 0) red_s[di * 4 + q] = s;
    __syncthreads();
    float S = red_s[di * 4 + 0] + red_s[di * 4 + 1] +
              red_s[di * 4 + 2] + red_s[di * 4 + 3];
    float inv = 1.f / S;

    const int t = q * 64 + 2 * lane;
    float w0 = p0 * inv, w1 = p1 * inv;
    sw4[(t + 0) * 4 + di] = w0;
    sw4[(t + 1) * 4 + di] = w1;
    float* erow = out_e + (size_t)(b * TD_ + d0 + di) * TE_;
    erow[t]     = w0;
    erow[t + 1] = w1;
    __syncthreads();

    // ---- context: thread owns h = tid, all 4 local d ----
    float c0 = 0.f, c1 = 0.f, c2 = 0.f, c3 = 0.f;
    const float* encb = enc + (size_t)b * TE_ * HE_;
    #pragma unroll 8
    for (int tt = 0; tt < TE_; tt++) {
        float ev = encb[tt * 512 + tid];
        float4 wv = *(const float4*)&sw4[tt * 4];
        c0 = fmaf(wv.x, ev, c0);
        c1 = fmaf(wv.y, ev, c1);
        c2 = fmaf(wv.z, ev, c2);
        c3 = fmaf(wv.w, ev, c3);
    }
    float* cbase = out_c + (size_t)(b * TD_ + d0) * HE_ + tid;
    cbase[0 * HE_] = c0;
    cbase[1 * HE_] = c1;
    cbase[2 * HE_] = c2;
    cbase[3 * HE_] = c3;
}

// ---------------------------------------------------------------------------
extern "C" void kernel_launch(void* const* d_in, const int* in_sizes, int n_in,
                              void* d_out, int out_size)
{
    const float* enc = (const float*)d_in[0];   // [8,256,512]
    const float* dec = (const float*)d_in[1];   // [8,128,512]
    const float* Wa  = (const float*)d_in[2];   // [512,512]
    const float* Ua  = (const float*)d_in[3];   // [512,512]
    const float* Va  = (const float*)d_in[4];   // [512,1]

    float* out   = (float*)d_out;
    float* out_c = out;                          // [8,128,512]
    float* out_e = out + B_ * TD_ * HE_;         // [8,128,256]

    gemm_kernel<<<384, 128>>>(enc, dec, Wa, Ua);
    attn_kernel<<<dim3(B_, TD_ / 4), 512>>>(enc, Va, out_c, out_e);
}